// round 3
// baseline (speedup 1.0000x reference)
#include <cuda_runtime.h>
#include <cuda_bf16.h>
#include <math.h>

// ---------------- problem constants ----------------
#define N0   120000
#define N1   12000
#define N2   1024
#define E1   300000
#define E2   10240
#define F_IN 602
#define H1   8
#define C1   8
#define HC   64        // H1*C1
#define NCLS 41
#define ET1  (E1 + N1) // edges + self loops, layer 1
#define ET2  (E2 + N2) // edges + self loops, layer 2
#define NEG_SLOPE 0.2f
#define KCHUNKS 38     // ceil(602/16)

// ---------------- scratch (__device__ globals; no allocs allowed) ----------------
__device__ float    g_h1[(size_t)N0 * HC];     // x @ W1
__device__ float    g_as1[(size_t)N0 * H1];    // (h * att_src1).sum(-1)
__device__ float    g_ad1[(size_t)N1 * H1];    // (h * att_dst1).sum(-1)
__device__ unsigned g_m1[(size_t)N1 * H1];     // ordered-uint segment max
__device__ float    g_s1[(size_t)N1 * H1];     // segment sum (-> reciprocal)
__device__ float    g_e1[(size_t)ET1 * H1];    // per-edge alpha / exp
__device__ int      g_src1[ET1];
__device__ int      g_dst1[ET1];
__device__ float    g_out1[(size_t)N1 * HC];   // layer-1 output (then ELU'd in place)
__device__ float    g_h2[(size_t)N1 * NCLS];   // h1 @ W2
__device__ float    g_as2[N1];
__device__ float    g_ad2[N2];
__device__ unsigned g_m2[N2];
__device__ float    g_s2[N2];
__device__ float    g_e2[ET2];
__device__ int      g_src2[ET2];
__device__ int      g_dst2[ET2];
__device__ float    g_out2[(size_t)N2 * NCLS];
__device__ int      g_is64;

// ---------------- helpers ----------------
__device__ __forceinline__ unsigned f2okey(float f) {
    unsigned u = __float_as_uint(f);
    return (u & 0x80000000u) ? ~u : (u | 0x80000000u);
}
__device__ __forceinline__ float okey2f(unsigned k) {
    return (k & 0x80000000u) ? __uint_as_float(k & 0x7FFFFFFFu)
                             : __uint_as_float(~k);
}
__device__ __forceinline__ int ldidx(const void* p, long i) {
    if (g_is64) return (int)((const long long*)p)[i];
    return ((const int*)p)[i];
}
__device__ __forceinline__ float lrelu(float x) {
    return x > 0.f ? x : NEG_SLOPE * x;
}
// split float into bf16 hi + bf16 lo (Dekker 2-term), pack pairs to u32
__device__ __forceinline__ void bfsplit(float v, __nv_bfloat16& h, __nv_bfloat16& l) {
    h = __float2bfloat16(v);
    l = __float2bfloat16(v - __bfloat162float(h));
}
__device__ __forceinline__ unsigned pack2(__nv_bfloat16 a, __nv_bfloat16 b) {
    unsigned short ua = __bfloat16_as_ushort(a), ub = __bfloat16_as_ushort(b);
    return ((unsigned)ub << 16) | (unsigned)ua;
}

__device__ __forceinline__ void mma_bf16(float& c0, float& c1, float& c2, float& c3,
                                         unsigned a0, unsigned a1, unsigned a2, unsigned a3,
                                         unsigned b0, unsigned b1) {
    asm volatile(
        "mma.sync.aligned.m16n8k16.row.col.f32.bf16.bf16.f32 "
        "{%0,%1,%2,%3},{%4,%5,%6,%7},{%8,%9},{%0,%1,%2,%3};"
        : "+f"(c0), "+f"(c1), "+f"(c2), "+f"(c3)
        : "r"(a0), "r"(a1), "r"(a2), "r"(a3), "r"(b0), "r"(b1));
}

// ---------------- kernels ----------------

__global__ void k_detect(const int* ei) {
    int z = 0;
    #pragma unroll
    for (int j = 1; j < 64; j += 2) z |= ei[j];
    g_is64 = (z == 0) ? 1 : 0;
}

__global__ void k_zero() {
    int i = blockIdx.x * blockDim.x + threadIdx.x;
    if (i < N1 * HC)   g_out1[i] = 0.f;
    if (i < N1 * H1) { g_s1[i] = 0.f; g_m1[i] = 0u; }
    if (i < N2 * NCLS) g_out2[i] = 0.f;
    if (i < N2)      { g_s2[i] = 0.f; g_m2[i] = 0u; }
}

// ============================================================================
// GEMM1: g_h1[120000,64] = x[120000,602] @ W1[602,64]
// Tensor cores: mma.sync m16n8k16 bf16, fp32 accumulate, 3-pass Dekker split
// (ah*bh + al*bh + ah*bl) -> ~2^-16 relative error per product.
// Block: 256 threads (8 warps as 4x2), tile M=128 N=64, K in chunks of 16.
// Double-buffered smem, register-staged global loads, 1 barrier per chunk.
// ============================================================================
__global__ __launch_bounds__(256) void k_gemm1(const float* __restrict__ A,
                                               const float* __restrict__ B) {
    // A tiles stored as packed bf16x2 words: [m][k/2], 128*8 words
    __shared__ unsigned sAh[2][128 * 8];
    __shared__ unsigned sAl[2][128 * 8];
    // B tiles stored n-major as bf16: [n][k], 64*16 halves (= 64*8 words)
    __shared__ __nv_bfloat16 sBh[2][64 * 16];
    __shared__ __nv_bfloat16 sBl[2][64 * 16];

    const int tid  = threadIdx.x;
    const int wid  = tid >> 5;
    const int lane = tid & 31;
    const int wm   = wid >> 1;   // 0..3
    const int wn   = wid & 1;    // 0..1
    const int lr   = lane >> 2;  // 0..7
    const int q    = lane & 3;   // 0..3
    const long r0  = (long)blockIdx.x * 128;

    // staging: A = 8 floats (4x float2), B = 4 floats (1x float4)
    const int am = tid >> 1;             // 0..127 : row within tile
    const int akh = (tid & 1) * 8;       // 0 or 8 : k base within chunk
    const int bk = tid >> 4;             // 0..15  : k within chunk
    const int bn0 = (tid & 15) * 4;      // 0..60  : n base

    float2 ast[4];
    float4 bst;

    auto loadA = [&](int k0) {
        long row = r0 + am;
        #pragma unroll
        for (int j = 0; j < 4; j++) {
            int gk = k0 + akh + j * 2;   // always even
            if (row < N0 && gk < F_IN - 1)
                ast[j] = *(const float2*)(A + row * F_IN + gk);
            else
                ast[j] = make_float2(0.f, 0.f);
        }
    };
    auto loadB = [&](int k0) {
        int gk = k0 + bk;
        if (gk < F_IN) bst = *(const float4*)(B + (long)gk * HC + bn0);
        else           bst = make_float4(0.f, 0.f, 0.f, 0.f);
    };
    auto stage = [&](int buf) {
        #pragma unroll
        for (int j = 0; j < 4; j++) {
            __nv_bfloat16 h0, l0, h1, l1;
            bfsplit(ast[j].x, h0, l0);
            bfsplit(ast[j].y, h1, l1);
            int w = am * 8 + (akh >> 1) + j;
            sAh[buf][w] = pack2(h0, h1);
            sAl[buf][w] = pack2(l0, l1);
        }
        float bv[4] = {bst.x, bst.y, bst.z, bst.w};
        #pragma unroll
        for (int j = 0; j < 4; j++) {
            __nv_bfloat16 h, l;
            bfsplit(bv[j], h, l);
            sBh[buf][(bn0 + j) * 16 + bk] = h;
            sBl[buf][(bn0 + j) * 16 + bk] = l;
        }
    };

    float acc[2][4][4];
    #pragma unroll
    for (int mt = 0; mt < 2; mt++)
        #pragma unroll
        for (int nt = 0; nt < 4; nt++)
            #pragma unroll
            for (int i = 0; i < 4; i++) acc[mt][nt][i] = 0.f;

    loadA(0);
    loadB(0);

    for (int ch = 0; ch < KCHUNKS; ch++) {
        int buf = ch & 1;
        stage(buf);
        __syncthreads();
        if (ch + 1 < KCHUNKS) { loadA((ch + 1) * 16); loadB((ch + 1) * 16); }

        // fragment loads
        unsigned ah[2][4], al[2][4], bhf[4][2], blf[4][2];
        #pragma unroll
        for (int mt = 0; mt < 2; mt++) {
            int r = wm * 32 + mt * 16 + lr;
            ah[mt][0] = sAh[buf][r * 8 + q];
            ah[mt][1] = sAh[buf][(r + 8) * 8 + q];
            ah[mt][2] = sAh[buf][r * 8 + q + 4];
            ah[mt][3] = sAh[buf][(r + 8) * 8 + q + 4];
            al[mt][0] = sAl[buf][r * 8 + q];
            al[mt][1] = sAl[buf][(r + 8) * 8 + q];
            al[mt][2] = sAl[buf][r * 8 + q + 4];
            al[mt][3] = sAl[buf][(r + 8) * 8 + q + 4];
        }
        const unsigned* bhw = (const unsigned*)sBh[buf];
        const unsigned* blw = (const unsigned*)sBl[buf];
        #pragma unroll
        for (int nt = 0; nt < 4; nt++) {
            int n = wn * 32 + nt * 8 + lr;
            bhf[nt][0] = bhw[n * 8 + q];
            bhf[nt][1] = bhw[n * 8 + q + 4];
            blf[nt][0] = blw[n * 8 + q];
            blf[nt][1] = blw[n * 8 + q + 4];
        }
        #pragma unroll
        for (int mt = 0; mt < 2; mt++)
            #pragma unroll
            for (int nt = 0; nt < 4; nt++) {
                float* c = acc[mt][nt];
                mma_bf16(c[0], c[1], c[2], c[3],
                         ah[mt][0], ah[mt][1], ah[mt][2], ah[mt][3],
                         bhf[nt][0], bhf[nt][1]);
                mma_bf16(c[0], c[1], c[2], c[3],
                         al[mt][0], al[mt][1], al[mt][2], al[mt][3],
                         bhf[nt][0], bhf[nt][1]);
                mma_bf16(c[0], c[1], c[2], c[3],
                         ah[mt][0], ah[mt][1], ah[mt][2], ah[mt][3],
                         blf[nt][0], blf[nt][1]);
            }
        // no trailing barrier: next iteration stages the other buffer, and the
        // pre-read barrier of iteration ch+1 orders any re-write of this buffer
        // (iteration ch+2) after all reads above.
    }

    // epilogue
    #pragma unroll
    for (int mt = 0; mt < 2; mt++) {
        #pragma unroll
        for (int nt = 0; nt < 4; nt++) {
            long r = r0 + wm * 32 + mt * 16 + lr;
            int c = wn * 32 + nt * 8 + q * 2;
            if (r < N0)
                *(float2*)(g_h1 + r * HC + c) =
                    make_float2(acc[mt][nt][0], acc[mt][nt][1]);
            if (r + 8 < N0)
                *(float2*)(g_h1 + (r + 8) * HC + c) =
                    make_float2(acc[mt][nt][2], acc[mt][nt][3]);
        }
    }
}

// Per-(node,head) attention scores: a_s for all N0 nodes, a_d for nodes < N1.
__global__ void k_att1(const float* __restrict__ asrc, const float* __restrict__ adst) {
    int t = blockIdx.x * blockDim.x + threadIdx.x;
    if (t >= N0 * H1) return;
    int node = t >> 3, h = t & 7;
    const float4* hp = (const float4*)(g_h1 + (long)node * HC + h * C1);
    float4 h0 = hp[0], h4 = hp[1];
    const float4* sp = (const float4*)(asrc + h * C1);
    float4 s0 = sp[0], s4 = sp[1];
    float as = h0.x*s0.x + h0.y*s0.y + h0.z*s0.z + h0.w*s0.w
             + h4.x*s4.x + h4.y*s4.y + h4.z*s4.z + h4.w*s4.w;
    g_as1[t] = as;
    if (node < N1) {
        const float4* dp = (const float4*)(adst + h * C1);
        float4 d0 = dp[0], d4 = dp[1];
        float ad = h0.x*d0.x + h0.y*d0.y + h0.z*d0.z + h0.w*d0.w
                 + h4.x*d4.x + h4.y*d4.y + h4.z*d4.z + h4.w*d4.w;
        g_ad1[t] = ad;
    }
}

__global__ void k_e1max(const void* __restrict__ ei) {
    int e = blockIdx.x * blockDim.x + threadIdx.x;
    if (e >= ET1) return;
    int src, dst;
    if (e < E1) { src = ldidx(ei, e); dst = ldidx(ei, (long)E1 + e); }
    else        { src = dst = e - E1; }
    g_src1[e] = src; g_dst1[e] = dst;
    const float4* sp = (const float4*)(g_as1 + (long)src * H1);
    const float4* dp = (const float4*)(g_ad1 + (long)dst * H1);
    float4 s0 = sp[0], s4 = sp[1], d0 = dp[0], d4 = dp[1];
    float a[8] = { lrelu(s0.x + d0.x), lrelu(s0.y + d0.y),
                   lrelu(s0.z + d0.z), lrelu(s0.w + d0.w),
                   lrelu(s4.x + d4.x), lrelu(s4.y + d4.y),
                   lrelu(s4.z + d4.z), lrelu(s4.w + d4.w) };
    #pragma unroll
    for (int h = 0; h < 8; h++) {
        g_e1[(long)e * H1 + h] = a[h];
        atomicMax(&g_m1[(long)dst * H1 + h], f2okey(a[h]));
    }
}

__global__ void k_e1sum() {
    int e = blockIdx.x * blockDim.x + threadIdx.x;
    if (e >= ET1) return;
    int dst = g_dst1[e];
    #pragma unroll
    for (int h = 0; h < 8; h++) {
        float m = okey2f(g_m1[(long)dst * H1 + h]);
        float ex = expf(g_e1[(long)e * H1 + h] - m);
        g_e1[(long)e * H1 + h] = ex;
        atomicAdd(&g_s1[(long)dst * H1 + h], ex);
    }
}

__global__ void k_rcp1() {
    int i = blockIdx.x * blockDim.x + threadIdx.x;
    if (i < N1 * H1) g_s1[i] = 1.f / (g_s1[i] + 1e-16f);
}

__global__ void k_e1scat() {
    long tid = (long)blockIdx.x * blockDim.x + threadIdx.x;
    if (tid >= (long)ET1 * 16) return;
    int e = (int)(tid >> 4);
    int t = (int)(tid & 15);
    int src = g_src1[e], dst = g_dst1[e];
    int h = t >> 1;
    float w = g_e1[(long)e * H1 + h] * g_s1[(long)dst * H1 + h];
    float4 hv = *(const float4*)(g_h1 + (long)src * HC + t * 4);
    float* ob = g_out1 + (long)dst * HC + t * 4;
    atomicAdd(ob + 0, hv.x * w);
    atomicAdd(ob + 1, hv.y * w);
    atomicAdd(ob + 2, hv.z * w);
    atomicAdd(ob + 3, hv.w * w);
}

__global__ void k_elu(const float* __restrict__ b1) {
    int i = blockIdx.x * blockDim.x + threadIdx.x;
    if (i >= N1 * HC) return;
    float v = g_out1[i] + b1[i & 63];
    g_out1[i] = v > 0.f ? v : expm1f(v);
}

__global__ __launch_bounds__(256) void k_gemm2(const float* __restrict__ W2) {
    __shared__ float Ws[HC * NCLS];
    int tid = threadIdx.x;
    for (int i = tid; i < HC * NCLS; i += 256) Ws[i] = W2[i];
    __syncthreads();
    int rbase = blockIdx.x * 32;
    for (int o = tid; o < 32 * NCLS; o += 256) {
        int r = o / NCLS, c = o - r * NCLS;
        int row = rbase + r;
        const float* hr = g_out1 + (long)row * HC;
        float acc = 0.f;
        #pragma unroll 16
        for (int k = 0; k < HC; k++) acc += hr[k] * Ws[k * NCLS + c];
        g_h2[(long)row * NCLS + c] = acc;
    }
}

__global__ void k_att2(const float* __restrict__ asrc, const float* __restrict__ adst) {
    int n = blockIdx.x * blockDim.x + threadIdx.x;
    if (n >= N1) return;
    const float* hr = g_h2 + (long)n * NCLS;
    float s = 0.f, d = 0.f;
    #pragma unroll
    for (int c = 0; c < NCLS; c++) {
        float v = hr[c];
        s += v * asrc[c];
        d += v * adst[c];
    }
    g_as2[n] = s;
    if (n < N2) g_ad2[n] = d;
}

__global__ void k_e2max(const void* __restrict__ ei) {
    int e = blockIdx.x * blockDim.x + threadIdx.x;
    if (e >= ET2) return;
    int src, dst;
    if (e < E2) { src = ldidx(ei, e); dst = ldidx(ei, (long)E2 + e); }
    else        { src = dst = e - E2; }
    g_src2[e] = src; g_dst2[e] = dst;
    float a = lrelu(g_as2[src] + g_ad2[dst]);
    g_e2[e] = a;
    atomicMax(&g_m2[dst], f2okey(a));
}

__global__ void k_e2sum() {
    int e = blockIdx.x * blockDim.x + threadIdx.x;
    if (e >= ET2) return;
    int dst = g_dst2[e];
    float ex = expf(g_e2[e] - okey2f(g_m2[dst]));
    g_e2[e] = ex;
    atomicAdd(&g_s2[dst], ex);
}

__global__ void k_rcp2() {
    int i = blockIdx.x * blockDim.x + threadIdx.x;
    if (i < N2) g_s2[i] = 1.f / (g_s2[i] + 1e-16f);
}

__global__ void k_e2scat() {
    int tid = blockIdx.x * blockDim.x + threadIdx.x;
    if (tid >= ET2 * NCLS) return;
    int e = tid / NCLS, c = tid - e * NCLS;
    int src = g_src2[e], dst = g_dst2[e];
    float w = g_e2[e] * g_s2[dst];
    atomicAdd(&g_out2[(long)dst * NCLS + c], g_h2[(long)src * NCLS + c] * w);
}

__global__ void k_logsm(const float* __restrict__ b2, float* __restrict__ out) {
    int row = blockIdx.x;
    int t = threadIdx.x;
    __shared__ float red[64];
    float v = -3.4e38f;
    if (t < NCLS) v = g_out2[(long)row * NCLS + t] + b2[t];
    red[t] = v;
    __syncthreads();
    for (int s = 32; s > 0; s >>= 1) {
        if (t < s) red[t] = fmaxf(red[t], red[t + s]);
        __syncthreads();
    }
    float m = red[0];
    __syncthreads();
    red[t] = (t < NCLS) ? expf(v - m) : 0.f;
    __syncthreads();
    for (int s = 32; s > 0; s >>= 1) {
        if (t < s) red[t] += red[t + s];
        __syncthreads();
    }
    float lse = m + logf(red[0]);
    if (t < NCLS) out[(long)row * NCLS + t] = v - lse;
}

// ---------------- launch ----------------
extern "C" void kernel_launch(void* const* d_in, const int* in_sizes, int n_in,
                              void* d_out, int out_size) {
    const float* x  = (const float*)d_in[0];
    const void* ei1 = d_in[1];
    const void* ei2 = d_in[2];

    int wi = 3;
    for (int i = 3; i < n_in; i++) {
        if (in_sizes[i] == F_IN * HC) { wi = i; break; }
    }
    const float* W1    = (const float*)d_in[wi];
    const float* asrc1 = (const float*)d_in[wi + 1];
    const float* adst1 = (const float*)d_in[wi + 2];
    const float* b1    = (const float*)d_in[wi + 3];
    const float* W2    = (const float*)d_in[wi + 4];
    const float* asrc2 = (const float*)d_in[wi + 5];
    const float* adst2 = (const float*)d_in[wi + 6];
    const float* b2    = (const float*)d_in[wi + 7];
    float* out = (float*)d_out;

    k_detect<<<1, 1>>>((const int*)ei1);
    k_zero<<<(N1 * HC + 255) / 256, 256>>>();
    k_gemm1<<<(N0 + 127) / 128, 256>>>(x, W1);
    k_att1<<<(N0 * H1 + 255) / 256, 256>>>(asrc1, adst1);
    k_e1max<<<(ET1 + 127) / 128, 128>>>(ei1);
    k_e1sum<<<(ET1 + 127) / 128, 128>>>();
    k_rcp1<<<(N1 * H1 + 255) / 256, 256>>>();
    k_e1scat<<<(int)(((long)ET1 * 16 + 255) / 256), 256>>>();
    k_elu<<<(N1 * HC + 255) / 256, 256>>>(b1);
    k_gemm2<<<N1 / 32, 256>>>(W2);
    k_att2<<<(N1 + 255) / 256, 256>>>(asrc2, adst2);
    k_e2max<<<(ET2 + 127) / 128, 128>>>(ei2);
    k_e2sum<<<(ET2 + 127) / 128, 128>>>();
    k_rcp2<<<(N2 + 255) / 256, 256>>>();
    k_e2scat<<<(ET2 * NCLS + 255) / 256, 256>>>();
    k_logsm<<<N2, 64>>>(b2, out);
    (void)out_size;
}

// round 5
// speedup vs baseline: 1.3094x; 1.3094x over previous
#include <cuda_runtime.h>
#include <cuda_bf16.h>
#include <math.h>

// ---------------- problem constants ----------------
#define N0   120000
#define N1   12000
#define N2   1024
#define E1   300000
#define E2   10240
#define F_IN 602
#define H1   8
#define C1   8
#define HC   64        // H1*C1
#define NCLS 41
#define ET1  (E1 + N1) // edges + self loops, layer 1
#define ET2  (E2 + N2) // edges + self loops, layer 2
#define NEG_SLOPE 0.2f
#define KCHUNKS 38     // ceil(602/16)

// ---------------- scratch (__device__ globals; no allocs allowed) ----------------
__device__ float g_h1[(size_t)N0 * HC];     // x @ W1
__device__ float g_as1[(size_t)N0 * H1];    // (h * att_src1).sum(-1)
__device__ float g_ad1[(size_t)N1 * H1];    // (h * att_dst1).sum(-1)
__device__ float g_out1[(size_t)N1 * HC];   // layer-1 output (bias+ELU fused)
__device__ float g_h2[(size_t)N1 * NCLS];   // out1 @ W2
__device__ float g_as2[N1];
__device__ float g_ad2[N2];
// CSR structures
__device__ int   g_rp1[N1 + 1];
__device__ int   g_cur1[N1];
__device__ int   g_csr1[ET1];
__device__ int   g_rp2[N2 + 1];
__device__ int   g_cur2[N2];
__device__ int   g_csr2[ET2];
__device__ int   g_is64;

// ---------------- helpers ----------------
__device__ __forceinline__ int ldidx(const void* p, long i) {
    if (g_is64) return (int)((const long long*)p)[i];
    return ((const int*)p)[i];
}
__device__ __forceinline__ float lrelu(float x) {
    return x > 0.f ? x : NEG_SLOPE * x;
}
__device__ __forceinline__ void bfsplit(float v, __nv_bfloat16& h, __nv_bfloat16& l) {
    h = __float2bfloat16(v);
    l = __float2bfloat16(v - __bfloat162float(h));
}
__device__ __forceinline__ unsigned pack2(__nv_bfloat16 a, __nv_bfloat16 b) {
    unsigned short ua = __bfloat16_as_ushort(a), ub = __bfloat16_as_ushort(b);
    return ((unsigned)ub << 16) | (unsigned)ua;
}
__device__ __forceinline__ void mma_bf16(float& c0, float& c1, float& c2, float& c3,
                                         unsigned a0, unsigned a1, unsigned a2, unsigned a3,
                                         unsigned b0, unsigned b1) {
    asm volatile(
        "mma.sync.aligned.m16n8k16.row.col.f32.bf16.bf16.f32 "
        "{%0,%1,%2,%3},{%4,%5,%6,%7},{%8,%9},{%0,%1,%2,%3};"
        : "+f"(c0), "+f"(c1), "+f"(c2), "+f"(c3)
        : "r"(a0), "r"(a1), "r"(a2), "r"(a3), "r"(b0), "r"(b1));
}

// ---------------- CSR build ----------------

__global__ void k_detect(const int* ei) {
    int z = 0;
    #pragma unroll
    for (int j = 1; j < 64; j += 2) z |= ei[j];
    g_is64 = (z == 0) ? 1 : 0;
}

// counts init to 1 (self-loop per dst node)
__global__ void k_cinit() {
    int i = blockIdx.x * blockDim.x + threadIdx.x;
    if (i < N1) g_cur1[i] = 1;
    if (i < N2) g_cur2[i] = 1;
}

__global__ void k_hist(const void* __restrict__ ei1, const void* __restrict__ ei2) {
    int t = blockIdx.x * blockDim.x + threadIdx.x;
    if (t < E1) {
        int dst = ldidx(ei1, (long)E1 + t);
        atomicAdd(&g_cur1[dst], 1);
    } else if (t < E1 + E2) {
        int e = t - E1;
        int dst = ldidx(ei2, (long)E2 + e);
        atomicAdd(&g_cur2[dst], 1);
    }
}

// exclusive scan; block 0 -> layer1, block 1 -> layer2. 1024 threads.
__global__ __launch_bounds__(1024) void k_scan() {
    __shared__ int sm[1024];
    const int n  = (blockIdx.x == 0) ? N1 : N2;
    int* cur     = (blockIdx.x == 0) ? g_cur1 : g_cur2;
    int* rp      = (blockIdx.x == 0) ? g_rp1  : g_rp2;
    const int t  = threadIdx.x;
    const int items = (n + 1023) / 1024;   // 12 or 1
    int loc[12];
    int tot = 0;
    for (int i = 0; i < items; i++) {
        int idx = t * items + i;
        int v = (idx < n) ? cur[idx] : 0;
        loc[i] = tot;
        tot += v;
    }
    sm[t] = tot;
    __syncthreads();
    for (int off = 1; off < 1024; off <<= 1) {
        int v = (t >= off) ? sm[t - off] : 0;
        __syncthreads();
        sm[t] += v;
        __syncthreads();
    }
    int excl = (t > 0) ? sm[t - 1] : 0;
    for (int i = 0; i < items; i++) {
        int idx = t * items + i;
        if (idx < n) {
            int o = excl + loc[i];
            rp[idx]  = o;
            cur[idx] = o;   // placement cursor
        }
    }
    if (t == 1023) rp[n] = sm[1023];
}

__global__ void k_place(const void* __restrict__ ei1, const void* __restrict__ ei2) {
    int t = blockIdx.x * blockDim.x + threadIdx.x;
    if (t < E1) {
        int src = ldidx(ei1, t);
        int dst = ldidx(ei1, (long)E1 + t);
        int pos = atomicAdd(&g_cur1[dst], 1);
        g_csr1[pos] = src;
    } else if (t < ET1) {
        int n = t - E1;
        int pos = atomicAdd(&g_cur1[n], 1);
        g_csr1[pos] = n;                    // self loop
    } else if (t < ET1 + E2) {
        int e = t - ET1;
        int src = ldidx(ei2, e);
        int dst = ldidx(ei2, (long)E2 + e);
        int pos = atomicAdd(&g_cur2[dst], 1);
        g_csr2[pos] = src;
    } else if (t < ET1 + ET2) {
        int n = t - ET1 - E2;
        int pos = atomicAdd(&g_cur2[n], 1);
        g_csr2[pos] = n;                    // self loop
    }
}

// ============================================================================
// GEMM1: g_h1[120000,64] = x[120000,602] @ W1[602,64]
// mma.sync m16n8k16 bf16, fp32 acc, 3-pass Dekker split.
// A staged via coalesced float2 loads: 8 lanes cover one row's 16-k chunk.
// ============================================================================
__global__ __launch_bounds__(256) void k_gemm1(const float* __restrict__ A,
                                               const float* __restrict__ B) {
    __shared__ unsigned sAh[2][128 * 8];
    __shared__ unsigned sAl[2][128 * 8];
    __shared__ __nv_bfloat16 sBh[2][64 * 16];
    __shared__ __nv_bfloat16 sBl[2][64 * 16];

    const int tid  = threadIdx.x;
    const int wid  = tid >> 5;
    const int lane = tid & 31;
    const int wm   = wid >> 1;
    const int wn   = wid & 1;
    const int lr   = lane >> 2;
    const int q    = lane & 3;
    const long r0  = (long)blockIdx.x * 128;

    const int bk  = tid >> 4;        // 0..15 : k within chunk (B)
    const int bn0 = (tid & 15) * 4;  // n base (B)

    float2 ast[4];
    float4 bst;

    auto loadA = [&](int k0) {
        #pragma unroll
        for (int i = 0; i < 4; i++) {
            int f = tid + i * 256;        // 0..1023 float2 slots
            long row = r0 + (f >> 3);
            int gk = k0 + (f & 7) * 2;    // even
            if (row < N0 && gk < F_IN)    // F_IN even -> full float2 valid
                ast[i] = *(const float2*)(A + row * F_IN + gk);
            else
                ast[i] = make_float2(0.f, 0.f);
        }
    };
    auto loadB = [&](int k0) {
        int gk = k0 + bk;
        if (gk < F_IN) bst = *(const float4*)(B + (long)gk * HC + bn0);
        else           bst = make_float4(0.f, 0.f, 0.f, 0.f);
    };
    auto stage = [&](int buf) {
        #pragma unroll
        for (int i = 0; i < 4; i++) {
            int f = tid + i * 256;
            int w = (f >> 3) * 8 + (f & 7);
            __nv_bfloat16 h0, l0, h1, l1;
            bfsplit(ast[i].x, h0, l0);
            bfsplit(ast[i].y, h1, l1);
            sAh[buf][w] = pack2(h0, h1);
            sAl[buf][w] = pack2(l0, l1);
        }
        float bv[4] = {bst.x, bst.y, bst.z, bst.w};
        #pragma unroll
        for (int j = 0; j < 4; j++) {
            __nv_bfloat16 h, l;
            bfsplit(bv[j], h, l);
            sBh[buf][(bn0 + j) * 16 + bk] = h;
            sBl[buf][(bn0 + j) * 16 + bk] = l;
        }
    };

    float acc[2][4][4];
    #pragma unroll
    for (int mt = 0; mt < 2; mt++)
        #pragma unroll
        for (int nt = 0; nt < 4; nt++)
            #pragma unroll
            for (int i = 0; i < 4; i++) acc[mt][nt][i] = 0.f;

    loadA(0);
    loadB(0);

    for (int ch = 0; ch < KCHUNKS; ch++) {
        int buf = ch & 1;
        stage(buf);
        __syncthreads();
        if (ch + 1 < KCHUNKS) { loadA((ch + 1) * 16); loadB((ch + 1) * 16); }

        unsigned ah[2][4], al[2][4], bhf[4][2], blf[4][2];
        #pragma unroll
        for (int mt = 0; mt < 2; mt++) {
            int r = wm * 32 + mt * 16 + lr;
            ah[mt][0] = sAh[buf][r * 8 + q];
            ah[mt][1] = sAh[buf][(r + 8) * 8 + q];
            ah[mt][2] = sAh[buf][r * 8 + q + 4];
            ah[mt][3] = sAh[buf][(r + 8) * 8 + q + 4];
            al[mt][0] = sAl[buf][r * 8 + q];
            al[mt][1] = sAl[buf][(r + 8) * 8 + q];
            al[mt][2] = sAl[buf][r * 8 + q + 4];
            al[mt][3] = sAl[buf][(r + 8) * 8 + q + 4];
        }
        const unsigned* bhw = (const unsigned*)sBh[buf];
        const unsigned* blw = (const unsigned*)sBl[buf];
        #pragma unroll
        for (int nt = 0; nt < 4; nt++) {
            int n = wn * 32 + nt * 8 + lr;
            bhf[nt][0] = bhw[n * 8 + q];
            bhf[nt][1] = bhw[n * 8 + q + 4];
            blf[nt][0] = blw[n * 8 + q];
            blf[nt][1] = blw[n * 8 + q + 4];
        }
        #pragma unroll
        for (int mt = 0; mt < 2; mt++)
            #pragma unroll
            for (int nt = 0; nt < 4; nt++) {
                float* c = acc[mt][nt];
                mma_bf16(c[0], c[1], c[2], c[3],
                         ah[mt][0], ah[mt][1], ah[mt][2], ah[mt][3],
                         bhf[nt][0], bhf[nt][1]);
                mma_bf16(c[0], c[1], c[2], c[3],
                         al[mt][0], al[mt][1], al[mt][2], al[mt][3],
                         bhf[nt][0], bhf[nt][1]);
                mma_bf16(c[0], c[1], c[2], c[3],
                         ah[mt][0], ah[mt][1], ah[mt][2], ah[mt][3],
                         blf[nt][0], blf[nt][1]);
            }
        __syncthreads();
    }

    #pragma unroll
    for (int mt = 0; mt < 2; mt++) {
        #pragma unroll
        for (int nt = 0; nt < 4; nt++) {
            long r = r0 + wm * 32 + mt * 16 + lr;
            int c = wn * 32 + nt * 8 + q * 2;
            if (r < N0)
                *(float2*)(g_h1 + r * HC + c) =
                    make_float2(acc[mt][nt][0], acc[mt][nt][1]);
            if (r + 8 < N0)
                *(float2*)(g_h1 + (r + 8) * HC + c) =
                    make_float2(acc[mt][nt][2], acc[mt][nt][3]);
        }
    }
}

// Per-(node,head) attention scores.
__global__ void k_att1(const float* __restrict__ asrc, const float* __restrict__ adst) {
    int t = blockIdx.x * blockDim.x + threadIdx.x;
    if (t >= N0 * H1) return;
    int node = t >> 3, h = t & 7;
    const float4* hp = (const float4*)(g_h1 + (long)node * HC + h * C1);
    float4 h0 = hp[0], h4 = hp[1];
    const float4* sp = (const float4*)(asrc + h * C1);
    float4 s0 = sp[0], s4 = sp[1];
    float as = h0.x*s0.x + h0.y*s0.y + h0.z*s0.z + h0.w*s0.w
             + h4.x*s4.x + h4.y*s4.y + h4.z*s4.z + h4.w*s4.w;
    g_as1[t] = as;
    if (node < N1) {
        const float4* dp = (const float4*)(adst + h * C1);
        float4 d0 = dp[0], d4 = dp[1];
        float ad = h0.x*d0.x + h0.y*d0.y + h0.z*d0.z + h0.w*d0.w
                 + h4.x*d4.x + h4.y*d4.y + h4.z*d4.z + h4.w*d4.w;
        g_ad1[t] = ad;
    }
}

// ============================================================================
// Layer-1 aggregation: one warp per dst node. CSR, no atomics.
// Pass 1: online softmax (max,sum) per head, 8 lanes/head x 4 edge slots.
// Pass 2: per-edge weight recomputed, h1[src] gathered coalesced (float2/lane),
// accumulated in registers; bias + ELU fused into the store.
// ============================================================================
__global__ __launch_bounds__(256) void k_agg1(const float* __restrict__ b1) {
    int warp = (blockIdx.x * blockDim.x + threadIdx.x) >> 5;
    if (warp >= N1) return;
    int lane = threadIdx.x & 31;
    int h = lane & 7;          // head for alpha computation
    int g = lane >> 3;         // edge slot 0..3 (pass 1)
    int beg = g_rp1[warp], end = g_rp1[warp + 1];
    float adv = g_ad1[(long)warp * 8 + h];

    // pass 1: online (m, s) per (g, h)
    float m = -1e30f, s = 0.f;
    for (int i = beg + g; i < end; i += 4) {
        int src = g_csr1[i];
        float a = lrelu(g_as1[(long)src * 8 + h] + adv);
        if (a > m) { s = s * __expf(m - a) + 1.f; m = a; }
        else       { s += __expf(a - m); }
    }
    // merge the 4 edge slots (xor 8, 16); sentinel -1e30 keeps exp well-defined
    #pragma unroll
    for (int off = 8; off <= 16; off <<= 1) {
        float mo = __shfl_xor_sync(0xFFFFFFFFu, m, off);
        float so = __shfl_xor_sync(0xFFFFFFFFu, s, off);
        float M = fmaxf(m, mo);
        s = s * __expf(m - M) + so * __expf(mo - M);
        m = M;
    }
    float r = 1.f / (s + 1e-16f);

    // pass 2: accumulate channels (2*lane, 2*lane+1); their head = lane>>2
    int c0 = lane * 2;
    int hs = lane >> 2;        // source lane holding w for this head
    float a0 = 0.f, a1 = 0.f;
    for (int i = beg; i < end; i++) {
        int src = g_csr1[i];
        float aa = lrelu(g_as1[(long)src * 8 + h] + adv);
        float w = __expf(aa - m) * r;                       // valid for head h=lane&7
        float wn = __shfl_sync(0xFFFFFFFFu, w, hs);
        float2 hv = *(const float2*)(g_h1 + (long)src * HC + c0);
        a0 += hv.x * wn;
        a1 += hv.y * wn;
    }
    a0 += b1[c0];
    a1 += b1[c0 + 1];
    a0 = a0 > 0.f ? a0 : expm1f(a0);
    a1 = a1 > 0.f ? a1 : expm1f(a1);
    *(float2*)(g_out1 + (long)warp * HC + c0) = make_float2(a0, a1);
}

__global__ __launch_bounds__(256) void k_gemm2(const float* __restrict__ W2) {
    __shared__ float Ws[HC * NCLS];
    int tid = threadIdx.x;
    for (int i = tid; i < HC * NCLS; i += 256) Ws[i] = W2[i];
    __syncthreads();
    int rbase = blockIdx.x * 32;
    for (int o = tid; o < 32 * NCLS; o += 256) {
        int r = o / NCLS, c = o - r * NCLS;
        int row = rbase + r;
        const float* hr = g_out1 + (long)row * HC;
        float acc = 0.f;
        #pragma unroll 16
        for (int k = 0; k < HC; k++) acc += hr[k] * Ws[k * NCLS + c];
        g_h2[(long)row * NCLS + c] = acc;
    }
}

__global__ void k_att2(const float* __restrict__ asrc, const float* __restrict__ adst) {
    int n = blockIdx.x * blockDim.x + threadIdx.x;
    if (n >= N1) return;
    const float* hr = g_h2 + (long)n * NCLS;
    float s = 0.f, d = 0.f;
    #pragma unroll
    for (int c = 0; c < NCLS; c++) {
        float v = hr[c];
        s += v * asrc[c];
        d += v * adst[c];
    }
    g_as2[n] = s;
    if (n < N2) g_ad2[n] = d;
}

// ============================================================================
// Layer-2 aggregation + bias + log-softmax, one warp per dst node.
// Lane l owns channels l and l+32 (l+32 valid for l<9).
// ============================================================================
__global__ __launch_bounds__(256) void k_agg2(const float* __restrict__ b2,
                                              float* __restrict__ out) {
    int warp = (blockIdx.x * blockDim.x + threadIdx.x) >> 5;
    if (warp >= N2) return;
    int lane = threadIdx.x & 31;
    int beg = g_rp2[warp], end = g_rp2[warp + 1];
    float adv = g_ad2[warp];

    // pass 1: online (m, s), lane-parallel over edges
    float m = -1e30f, s = 0.f;
    for (int i = beg + lane; i < end; i += 32) {
        float a = lrelu(g_as2[g_csr2[i]] + adv);
        if (a > m) { s = s * __expf(m - a) + 1.f; m = a; }
        else       { s += __expf(a - m); }
    }
    #pragma unroll
    for (int off = 1; off <= 16; off <<= 1) {
        float mo = __shfl_xor_sync(0xFFFFFFFFu, m, off);
        float so = __shfl_xor_sync(0xFFFFFFFFu, s, off);
        float M = fmaxf(m, mo);
        s = s * __expf(m - M) + so * __expf(mo - M);
        m = M;
    }
    float r = 1.f / (s + 1e-16f);

    // pass 2: accumulate
    float a0 = 0.f, a1 = 0.f;
    bool has2 = (lane + 32) < NCLS;
    for (int i = beg; i < end; i++) {
        int src = g_csr2[i];
        float w = __expf(lrelu(g_as2[src] + adv) - m) * r;  // same on all lanes
        const float* hr = g_h2 + (long)src * NCLS;
        a0 += hr[lane] * w;
        if (has2) a1 += hr[lane + 32] * w;
    }
    float v0 = a0 + b2[lane];
    float v1 = has2 ? (a1 + b2[lane + 32]) : -1e30f;

    // row log-softmax over 41 values
    float mm = fmaxf(v0, v1);
    #pragma unroll
    for (int off = 1; off <= 16; off <<= 1)
        mm = fmaxf(mm, __shfl_xor_sync(0xFFFFFFFFu, mm, off));
    float e = __expf(v0 - mm) + (has2 ? __expf(v1 - mm) : 0.f);
    #pragma unroll
    for (int off = 1; off <= 16; off <<= 1)
        e += __shfl_xor_sync(0xFFFFFFFFu, e, off);
    float lse = mm + logf(e);
    out[(long)warp * NCLS + lane] = v0 - lse;
    if (has2) out[(long)warp * NCLS + lane + 32] = v1 - lse;
}

// ---------------- launch ----------------
extern "C" void kernel_launch(void* const* d_in, const int* in_sizes, int n_in,
                              void* d_out, int out_size) {
    const float* x  = (const float*)d_in[0];
    const void* ei1 = d_in[1];
    const void* ei2 = d_in[2];

    int wi = 3;
    for (int i = 3; i < n_in; i++) {
        if (in_sizes[i] == F_IN * HC) { wi = i; break; }
    }
    const float* W1    = (const float*)d_in[wi];
    const float* asrc1 = (const float*)d_in[wi + 1];
    const float* adst1 = (const float*)d_in[wi + 2];
    const float* b1    = (const float*)d_in[wi + 3];
    const float* W2    = (const float*)d_in[wi + 4];
    const float* asrc2 = (const float*)d_in[wi + 5];
    const float* adst2 = (const float*)d_in[wi + 6];
    const float* b2    = (const float*)d_in[wi + 7];
    float* out = (float*)d_out;

    k_detect<<<1, 1>>>((const int*)ei1);
    k_cinit<<<(N1 + 255) / 256, 256>>>();
    k_hist<<<(E1 + E2 + 255) / 256, 256>>>(ei1, ei2);
    k_scan<<<2, 1024>>>();
    k_place<<<(ET1 + ET2 + 255) / 256, 256>>>(ei1, ei2);
    k_gemm1<<<(N0 + 127) / 128, 256>>>(x, W1);
    k_att1<<<(N0 * H1 + 255) / 256, 256>>>(asrc1, adst1);
    k_agg1<<<(N1 * 32 + 255) / 256, 256>>>(b1);
    k_gemm2<<<N1 / 32, 256>>>(W2);
    k_att2<<<(N1 + 255) / 256, 256>>>(asrc2, adst2);
    k_agg2<<<(N2 * 32 + 255) / 256, 256>>>(b2, out);
    (void)out_size;
}